// round 2
// baseline (speedup 1.0000x reference)
#include <cuda_runtime.h>
#include <math.h>

#define Bb 512
#define Nn 1024
#define Pp 1024
#define Kk 1024
#define Tt 32
#define EPSV 1e-10f

// scratch (no allocations allowed)
__device__ float g_a[Bb * Nn];     // relu activations
__device__ float g_asig[Bb * Nn];  // sigmoid-rescaled activations
__device__ float g_acc[4];         // 0: recon sq-sum, 1: entropy sum, 2: decay sq-sum

__global__ void init_kernel() {
    if (threadIdx.x < 4) g_acc[threadIdx.x] = 0.f;
}

// ---------------------------------------------------------------------------
// GEMM1: a = relu(x @ w_enc + b_enc); also a_sig = 2/(1+exp(-a)) - 1
// 64x64 tile, 256 threads, 4x4 per thread, BK=16
// ---------------------------------------------------------------------------
__global__ __launch_bounds__(256) void gemm_enc(const float* __restrict__ X,
                                                const float* __restrict__ W,
                                                const float* __restrict__ bias) {
    __shared__ __align__(16) float As[16][64];
    __shared__ __align__(16) float Bs[16][64];
    int t = threadIdx.x;
    int m0 = blockIdx.y * 64, n0 = blockIdx.x * 64;
    int arow = t >> 2, acol = (t & 3) << 2;
    int brow = t >> 4, bcol = (t & 15) << 2;
    int ry = (t >> 4) << 2, rx = (t & 15) << 2;
    float acc[4][4] = {};
    for (int k0 = 0; k0 < Kk; k0 += 16) {
        float4 av = *(const float4*)(X + (m0 + arow) * Kk + k0 + acol);
        float4 bv = *(const float4*)(W + (k0 + brow) * Nn + n0 + bcol);
        __syncthreads();
        As[acol + 0][arow] = av.x; As[acol + 1][arow] = av.y;
        As[acol + 2][arow] = av.z; As[acol + 3][arow] = av.w;
        *(float4*)(&Bs[brow][bcol]) = bv;
        __syncthreads();
#pragma unroll
        for (int k = 0; k < 16; k++) {
            float4 a4 = *(float4*)(&As[k][ry]);
            float4 b4 = *(float4*)(&Bs[k][rx]);
            float am[4] = {a4.x, a4.y, a4.z, a4.w};
            float bn[4] = {b4.x, b4.y, b4.z, b4.w};
#pragma unroll
            for (int i = 0; i < 4; i++)
#pragma unroll
                for (int j = 0; j < 4; j++)
                    acc[i][j] = fmaf(am[i], bn[j], acc[i][j]);
        }
    }
#pragma unroll
    for (int i = 0; i < 4; i++) {
        int m = m0 + ry + i;
#pragma unroll
        for (int j = 0; j < 4; j++) {
            int n = n0 + rx + j;
            float v = acc[i][j] + bias[n];
            float a = fmaxf(v, 0.f);
            g_a[m * Nn + n] = a;
            g_asig[m * Nn + n] = 2.f / (1.f + expf(-a)) - 1.f;
        }
    }
}

// ---------------------------------------------------------------------------
// GEMM2: x_hat = a @ w_dec + b_dec ; accumulate sum((x-x_hat)^2)
// ---------------------------------------------------------------------------
__global__ __launch_bounds__(256) void gemm_dec(const float* __restrict__ W,
                                                const float* __restrict__ bias,
                                                const float* __restrict__ X,
                                                float* __restrict__ xhat) {
    __shared__ __align__(16) float As[16][64];
    __shared__ __align__(16) float Bs[16][64];
    int t = threadIdx.x;
    int m0 = blockIdx.y * 64, n0 = blockIdx.x * 64;
    int arow = t >> 2, acol = (t & 3) << 2;
    int brow = t >> 4, bcol = (t & 15) << 2;
    int ry = (t >> 4) << 2, rx = (t & 15) << 2;
    float acc[4][4] = {};
    for (int k0 = 0; k0 < Nn; k0 += 16) {
        float4 av = *(const float4*)(g_a + (m0 + arow) * Nn + k0 + acol);
        float4 bv = *(const float4*)(W + (k0 + brow) * Pp + n0 + bcol);
        __syncthreads();
        As[acol + 0][arow] = av.x; As[acol + 1][arow] = av.y;
        As[acol + 2][arow] = av.z; As[acol + 3][arow] = av.w;
        *(float4*)(&Bs[brow][bcol]) = bv;
        __syncthreads();
#pragma unroll
        for (int k = 0; k < 16; k++) {
            float4 a4 = *(float4*)(&As[k][ry]);
            float4 b4 = *(float4*)(&Bs[k][rx]);
            float am[4] = {a4.x, a4.y, a4.z, a4.w};
            float bn[4] = {b4.x, b4.y, b4.z, b4.w};
#pragma unroll
            for (int i = 0; i < 4; i++)
#pragma unroll
                for (int j = 0; j < 4; j++)
                    acc[i][j] = fmaf(am[i], bn[j], acc[i][j]);
        }
    }
    float lsum = 0.f;
#pragma unroll
    for (int i = 0; i < 4; i++) {
        int m = m0 + ry + i;
#pragma unroll
        for (int j = 0; j < 4; j++) {
            int n = n0 + rx + j;
            float v = acc[i][j] + bias[n];
            xhat[m * Pp + n] = v;
            float d = X[m * Pp + n] - v;
            lsum = fmaf(d, d, lsum);
        }
    }
#pragma unroll
    for (int o = 16; o > 0; o >>= 1) lsum += __shfl_xor_sync(~0u, lsum, o);
    __shared__ float red[8];
    if ((t & 31) == 0) red[t >> 5] = lsum;
    __syncthreads();
    if (t == 0) {
        float tot = 0.f;
#pragma unroll
        for (int i = 0; i < 8; i++) tot += red[i];
        atomicAdd(&g_acc[0], tot);
    }
}

// ---------------------------------------------------------------------------
// MLE: per-neuron 15-step gradient ascent on thetas + entropy.
// One warp per neuron; 16 samples per lane cached in registers.
// Triangle basis == linear interpolation weights over 2 adjacent centers.
// ---------------------------------------------------------------------------
__global__ __launch_bounds__(128) void mle_kernel(const float* __restrict__ thetas,
                                                  const float* __restrict__ centers,
                                                  float* __restrict__ ent_out) {
    __shared__ float s_pi[4][32];
    __shared__ float s_G[4][32];
    __shared__ float s_c[32];
    int tid = threadIdx.x;
    int warp = tid >> 5, lane = tid & 31;
    if (tid < 32) s_c[tid] = centers[tid];
    __syncthreads();
    int n = blockIdx.x * 4 + warp;
    float c0 = s_c[0];
    float width = s_c[1] - s_c[0];
    float invw = 1.0f / width;

    // preload sample bins for this neuron
    int t0[16];
    float w0[16], w1[16];
#pragma unroll
    for (int i = 0; i < 16; i++) {
        int b = i * 32 + lane;
        float as = g_asig[b * Nn + n];
        float xf = (as - c0) * invw;
        int tt = (int)floorf(xf);
        tt = min(max(tt, 0), 30);
        t0[i] = tt;
        w0[i] = fmaxf(0.f, 1.f - fabsf(as - s_c[tt]) * invw);
        w1[i] = fmaxf(0.f, 1.f - fabsf(as - s_c[tt + 1]) * invw);
    }

    float th = thetas[n * Tt + lane];
    float* pi = s_pi[warp];
    float* G = s_G[warp];

    for (int step = 0; step < 15; step++) {
        // softmax over T=32 (one value per lane), max-subtracted like jax
        float m = th;
#pragma unroll
        for (int o = 16; o > 0; o >>= 1) m = fmaxf(m, __shfl_xor_sync(~0u, m, o));
        float e = expf(th - m);
        float sum = e;
#pragma unroll
        for (int o = 16; o > 0; o >>= 1) sum += __shfl_xor_sync(~0u, sum, o);
        float p_l = e / sum;
        pi[lane] = p_l;
        G[lane] = 0.f;
        __syncwarp();

        float s_acc = 0.f;
#pragma unroll
        for (int i = 0; i < 16; i++) {
            float p = w0[i] * pi[t0[i]] + w1[i] * pi[t0[i] + 1];
            float r = 1.0f / (p + EPSV);
            atomicAdd(&G[t0[i]], w0[i] * r);
            atomicAdd(&G[t0[i] + 1], w1[i] * r);
            s_acc = fmaf(p, r, s_acc);
        }
#pragma unroll
        for (int o = 16; o > 0; o >>= 1) s_acc += __shfl_xor_sync(~0u, s_acc, o);
        __syncwarp();
        th += 0.01f * (p_l * (G[lane] - s_acc));
        __syncwarp();
    }

    // final softmax + per-neuron entropy over batch
    float m = th;
#pragma unroll
    for (int o = 16; o > 0; o >>= 1) m = fmaxf(m, __shfl_xor_sync(~0u, m, o));
    float e = expf(th - m);
    float sum = e;
#pragma unroll
    for (int o = 16; o > 0; o >>= 1) sum += __shfl_xor_sync(~0u, sum, o);
    pi[lane] = e / sum;
    __syncwarp();

    float ent = 0.f;
#pragma unroll
    for (int i = 0; i < 16; i++) {
        float p = w0[i] * pi[t0[i]] + w1[i] * pi[t0[i] + 1];
        ent -= p * logf(p + EPSV);
    }
#pragma unroll
    for (int o = 16; o > 0; o >>= 1) ent += __shfl_xor_sync(~0u, ent, o);
    if (lane == 0) {
        ent_out[n] = ent;
        atomicAdd(&g_acc[1], ent);
    }
}

// ---------------------------------------------------------------------------
// decay: sum(w_enc^2) + sum(w_dec^2)
// ---------------------------------------------------------------------------
__global__ __launch_bounds__(256) void decay_kernel(const float* __restrict__ we,
                                                    const float* __restrict__ wd) {
    float s = 0.f;
    for (int i = blockIdx.x * blockDim.x + threadIdx.x; i < Nn * Pp;
         i += gridDim.x * blockDim.x) {
        float a = we[i]; s = fmaf(a, a, s);
        float b = wd[i]; s = fmaf(b, b, s);
    }
#pragma unroll
    for (int o = 16; o > 0; o >>= 1) s += __shfl_xor_sync(~0u, s, o);
    __shared__ float red[8];
    if ((threadIdx.x & 31) == 0) red[threadIdx.x >> 5] = s;
    __syncthreads();
    if (threadIdx.x == 0) {
        float tot = 0.f;
#pragma unroll
        for (int i = 0; i < 8; i++) tot += red[i];
        atomicAdd(&g_acc[2], tot);
    }
}

__global__ void finalize_kernel(float* __restrict__ out) {
    // recon = mean_b 0.5*rowsum ; entropy_loss = 0.01*sum(ent)
    // decay = 0.5*0.001*(0.5*swe + 0.5*swd) = 0.00025*(swe+swd)
    out[Bb * Pp + Nn] = (0.5f / (float)Bb) * g_acc[0] + 0.01f * g_acc[1] +
                        0.00025f * g_acc[2];
}

extern "C" void kernel_launch(void* const* d_in, const int* in_sizes, int n_in,
                              void* d_out, int out_size) {
    const float* x   = (const float*)d_in[0];
    const float* we  = (const float*)d_in[1];
    const float* be  = (const float*)d_in[2];
    const float* wd  = (const float*)d_in[3];
    const float* bd  = (const float*)d_in[4];
    const float* th  = (const float*)d_in[5];
    const float* cen = (const float*)d_in[6];
    float* out = (float*)d_out;

    init_kernel<<<1, 32>>>();
    gemm_enc<<<dim3(Nn / 64, Bb / 64), 256>>>(x, we, be);
    mle_kernel<<<Nn / 4, 128>>>(th, cen, out + Bb * Pp);
    decay_kernel<<<256, 256>>>(we, wd);
    gemm_dec<<<dim3(Pp / 64, Bb / 64), 256>>>(wd, bd, x, out);
    finalize_kernel<<<1, 1>>>(out);
}

// round 3
// speedup vs baseline: 2.5496x; 2.5496x over previous
#include <cuda_runtime.h>
#include <math.h>

#define Bb 512
#define Nn 1024
#define Pp 1024
#define Kk 1024
#define Tt 32
#define EPSV 1e-10f

// scratch (no allocations allowed)
__device__ float g_a[Bb * Nn];      // relu activations, row-major [B,N]
__device__ float g_asigT[Nn * Bb];  // sigmoid activations, TRANSPOSED [N,B]
__device__ float g_acc[4];          // 0: recon sq-sum, 1: entropy sum, 2: decay sq-sum

// ---------------------------------------------------------------------------
// GEMM1: a = relu(x @ w_enc + b_enc); a_sigT = 2/(1+exp(-a)) - 1 (transposed)
// 64x64 tile, 256 threads, 4x4 per thread, BK=16, register-prefetch pipeline
// ---------------------------------------------------------------------------
__global__ __launch_bounds__(256) void gemm_enc(const float* __restrict__ X,
                                                const float* __restrict__ W,
                                                const float* __restrict__ bias) {
    __shared__ __align__(16) float As[16][68];
    __shared__ __align__(16) float Bs[16][64];
    int t = threadIdx.x;
    if (blockIdx.x == 0 && blockIdx.y == 0 && t < 4) g_acc[t] = 0.f;
    int m0 = blockIdx.y * 64, n0 = blockIdx.x * 64;
    int arow = t >> 2, acol = (t & 3) << 2;
    int brow = t >> 4, bcol = (t & 15) << 2;
    int ry = (t >> 4) << 2, rx = (t & 15) << 2;
    float acc[4][4] = {};
    const float* ap = X + (m0 + arow) * Kk + acol;
    const float* bp = W + brow * Nn + n0 + bcol;
    float4 av = *(const float4*)ap;
    float4 bv = *(const float4*)bp;
    for (int k0 = 0; k0 < Kk; k0 += 16) {
        __syncthreads();
        As[acol + 0][arow] = av.x; As[acol + 1][arow] = av.y;
        As[acol + 2][arow] = av.z; As[acol + 3][arow] = av.w;
        *(float4*)(&Bs[brow][bcol]) = bv;
        __syncthreads();
        if (k0 + 16 < Kk) {
            av = *(const float4*)(ap + k0 + 16);
            bv = *(const float4*)(bp + (k0 + 16) * Nn);
        }
#pragma unroll
        for (int k = 0; k < 16; k++) {
            float4 a4 = *(float4*)(&As[k][ry]);
            float4 b4 = *(float4*)(&Bs[k][rx]);
            float am[4] = {a4.x, a4.y, a4.z, a4.w};
            float bn[4] = {b4.x, b4.y, b4.z, b4.w};
#pragma unroll
            for (int i = 0; i < 4; i++)
#pragma unroll
                for (int j = 0; j < 4; j++)
                    acc[i][j] = fmaf(am[i], bn[j], acc[i][j]);
        }
    }
#pragma unroll
    for (int i = 0; i < 4; i++) {
        int m = m0 + ry + i;
#pragma unroll
        for (int j = 0; j < 4; j++) {
            int n = n0 + rx + j;
            float v = acc[i][j] + bias[n];
            float a = fmaxf(v, 0.f);
            g_a[m * Nn + n] = a;
            float e = __expf(-a);
            g_asigT[n * Bb + m] = __fdividef(2.f, 1.f + e) - 1.f;
        }
    }
}

// ---------------------------------------------------------------------------
// GEMM2: x_hat = a @ w_dec + b_dec ; accumulate sum((x-x_hat)^2)
// ---------------------------------------------------------------------------
__global__ __launch_bounds__(256) void gemm_dec(const float* __restrict__ W,
                                                const float* __restrict__ bias,
                                                const float* __restrict__ X,
                                                float* __restrict__ xhat) {
    __shared__ __align__(16) float As[16][68];
    __shared__ __align__(16) float Bs[16][64];
    int t = threadIdx.x;
    int m0 = blockIdx.y * 64, n0 = blockIdx.x * 64;
    int arow = t >> 2, acol = (t & 3) << 2;
    int brow = t >> 4, bcol = (t & 15) << 2;
    int ry = (t >> 4) << 2, rx = (t & 15) << 2;
    float acc[4][4] = {};
    const float* ap = g_a + (m0 + arow) * Nn + acol;
    const float* bp = W + brow * Pp + n0 + bcol;
    float4 av = *(const float4*)ap;
    float4 bv = *(const float4*)bp;
    for (int k0 = 0; k0 < Nn; k0 += 16) {
        __syncthreads();
        As[acol + 0][arow] = av.x; As[acol + 1][arow] = av.y;
        As[acol + 2][arow] = av.z; As[acol + 3][arow] = av.w;
        *(float4*)(&Bs[brow][bcol]) = bv;
        __syncthreads();
        if (k0 + 16 < Nn) {
            av = *(const float4*)(ap + k0 + 16);
            bv = *(const float4*)(bp + (k0 + 16) * Pp);
        }
#pragma unroll
        for (int k = 0; k < 16; k++) {
            float4 a4 = *(float4*)(&As[k][ry]);
            float4 b4 = *(float4*)(&Bs[k][rx]);
            float am[4] = {a4.x, a4.y, a4.z, a4.w};
            float bn[4] = {b4.x, b4.y, b4.z, b4.w};
#pragma unroll
            for (int i = 0; i < 4; i++)
#pragma unroll
                for (int j = 0; j < 4; j++)
                    acc[i][j] = fmaf(am[i], bn[j], acc[i][j]);
        }
    }
    float lsum = 0.f;
#pragma unroll
    for (int i = 0; i < 4; i++) {
        int m = m0 + ry + i;
#pragma unroll
        for (int j = 0; j < 4; j++) {
            int n = n0 + rx + j;
            float v = acc[i][j] + bias[n];
            xhat[m * Pp + n] = v;
            float d = X[m * Pp + n] - v;
            lsum = fmaf(d, d, lsum);
        }
    }
#pragma unroll
    for (int o = 16; o > 0; o >>= 1) lsum += __shfl_xor_sync(~0u, lsum, o);
    __shared__ float red[8];
    if ((t & 31) == 0) red[t >> 5] = lsum;
    __syncthreads();
    if (t == 0) {
        float tot = 0.f;
#pragma unroll
        for (int i = 0; i < 8; i++) tot += red[i];
        atomicAdd(&g_acc[0], tot);
    }
}

// ---------------------------------------------------------------------------
// MLE: per-neuron 15-step gradient ascent on thetas + entropy.
// One warp per neuron; 16 samples/lane in registers; exact-0 and exact-1
// clusters handled analytically (they are ~65% of samples and were the
// same-address ATOMS hotspot); residual scatter uses 4-way replicated,
// bank-padded G.
// ---------------------------------------------------------------------------
__global__ __launch_bounds__(128) void mle_kernel(const float* __restrict__ thetas,
                                                  const float* __restrict__ centers,
                                                  float* __restrict__ ent_out) {
    __shared__ float s_pi[4][32];
    __shared__ float s_G[4][4 * 33];  // [warp][replica*33 + bin], bank-padded
    __shared__ float s_c[32];
    int tid = threadIdx.x;
    int warp = tid >> 5, lane = tid & 31;
    if (tid < 32) s_c[tid] = centers[tid];
    __syncthreads();
    int n = blockIdx.x * 4 + warp;
    float c0 = s_c[0];
    float invw = __fdividef(1.0f, s_c[1] - s_c[0]);

    // preload sample bins for this neuron (coalesced from transposed a_sig)
    const float* col = g_asigT + n * Bb;
    int t0[16];
    float w0[16], w1[16];
    unsigned zbits = 0, obits = 0;
    int zc = 0, oc = 0;
#pragma unroll
    for (int i = 0; i < 16; i++) {
        float as = col[i * 32 + lane];
        if (as == 0.f) { zbits |= 1u << i; zc++; }
        else if (as == 1.f) { obits |= 1u << i; oc++; }
        float xf = (as - c0) * invw;
        int tt = (int)floorf(xf);
        tt = min(max(tt, 0), 30);
        t0[i] = tt;
        w0[i] = fmaxf(0.f, 1.f - fabsf(as - s_c[tt]) * invw);
        w1[i] = fmaxf(0.f, 1.f - fabsf(as - s_c[tt + 1]) * invw);
    }
    int ztot = zc, otot = oc;
#pragma unroll
    for (int o = 16; o > 0; o >>= 1) {
        ztot += __shfl_xor_sync(~0u, ztot, o);
        otot += __shfl_xor_sync(~0u, otot, o);
    }
    // cluster weights (as = 0 -> bins 15/16 ; as = 1 -> bins 30/31)
    float w0z = fmaxf(0.f, 1.f - fabsf(s_c[15]) * invw);
    float w1z = fmaxf(0.f, 1.f - fabsf(s_c[16]) * invw);
    float w0o = fmaxf(0.f, 1.f - fabsf(1.f - s_c[30]) * invw);
    float w1o = fmaxf(0.f, 1.f - fabsf(1.f - s_c[31]) * invw);
    float zf = (float)ztot, of = (float)otot;

    float th = thetas[n * Tt + lane];
    float* pi = s_pi[warp];
    float* G = s_G[warp];
    int rep = (lane & 3) * 33;
    unsigned skip = zbits | obits;

    for (int step = 0; step < 15; step++) {
        float m = th;
#pragma unroll
        for (int o = 16; o > 0; o >>= 1) m = fmaxf(m, __shfl_xor_sync(~0u, m, o));
        float e = __expf(th - m);
        float sum = e;
#pragma unroll
        for (int o = 16; o > 0; o >>= 1) sum += __shfl_xor_sync(~0u, sum, o);
        float p_l = __fdividef(e, sum);
        pi[lane] = p_l;
        G[0 * 33 + lane] = 0.f; G[1 * 33 + lane] = 0.f;
        G[2 * 33 + lane] = 0.f; G[3 * 33 + lane] = 0.f;
        __syncwarp();

        float s_acc = 0.f;
        // analytic clusters
        if (lane == 0 && ztot > 0) {
            float pz = w0z * pi[15] + w1z * pi[16];
            float rz = __fdividef(1.f, pz + EPSV);
            atomicAdd(&G[0 * 33 + 15], zf * w0z * rz);
            atomicAdd(&G[0 * 33 + 16], zf * w1z * rz);
            s_acc += zf * pz * rz;
        }
        if (lane == 1 && otot > 0) {
            float po = w0o * pi[30] + w1o * pi[31];
            float ro = __fdividef(1.f, po + EPSV);
            atomicAdd(&G[1 * 33 + 30], of * w0o * ro);
            atomicAdd(&G[1 * 33 + 31], of * w1o * ro);
            s_acc += of * po * ro;
        }
        // residual samples
#pragma unroll
        for (int i = 0; i < 16; i++) {
            if (!((skip >> i) & 1u)) {
                float p = w0[i] * pi[t0[i]] + w1[i] * pi[t0[i] + 1];
                float r = __fdividef(1.f, p + EPSV);
                atomicAdd(&G[rep + t0[i]], w0[i] * r);
                atomicAdd(&G[rep + t0[i] + 1], w1[i] * r);
                s_acc = fmaf(p, r, s_acc);
            }
        }
#pragma unroll
        for (int o = 16; o > 0; o >>= 1) s_acc += __shfl_xor_sync(~0u, s_acc, o);
        __syncwarp();
        float g = G[0 * 33 + lane] + G[1 * 33 + lane] +
                  G[2 * 33 + lane] + G[3 * 33 + lane];
        th += 0.01f * (p_l * (g - s_acc));
        __syncwarp();
    }

    // final softmax + per-neuron entropy over batch
    float m = th;
#pragma unroll
    for (int o = 16; o > 0; o >>= 1) m = fmaxf(m, __shfl_xor_sync(~0u, m, o));
    float e = __expf(th - m);
    float sum = e;
#pragma unroll
    for (int o = 16; o > 0; o >>= 1) sum += __shfl_xor_sync(~0u, sum, o);
    pi[lane] = __fdividef(e, sum);
    __syncwarp();

    float ent = 0.f;
    if (lane == 0 && ztot > 0) {
        float pz = w0z * pi[15] + w1z * pi[16];
        ent -= zf * pz * __logf(pz + EPSV);
    }
    if (lane == 1 && otot > 0) {
        float po = w0o * pi[30] + w1o * pi[31];
        ent -= of * po * __logf(po + EPSV);
    }
#pragma unroll
    for (int i = 0; i < 16; i++) {
        if (!((skip >> i) & 1u)) {
            float p = w0[i] * pi[t0[i]] + w1[i] * pi[t0[i] + 1];
            ent -= p * __logf(p + EPSV);
        }
    }
#pragma unroll
    for (int o = 16; o > 0; o >>= 1) ent += __shfl_xor_sync(~0u, ent, o);
    if (lane == 0) {
        ent_out[n] = ent;
        atomicAdd(&g_acc[1], ent);
    }
}

// ---------------------------------------------------------------------------
// decay: sum(w_enc^2) + sum(w_dec^2), vectorized
// ---------------------------------------------------------------------------
__global__ __launch_bounds__(256) void decay_kernel(const float* __restrict__ we,
                                                    const float* __restrict__ wd) {
    float s = 0.f;
    const float4* we4 = (const float4*)we;
    const float4* wd4 = (const float4*)wd;
    int nv = (Nn * Pp) / 4;
    for (int i = blockIdx.x * blockDim.x + threadIdx.x; i < nv;
         i += gridDim.x * blockDim.x) {
        float4 a = we4[i];
        s = fmaf(a.x, a.x, s); s = fmaf(a.y, a.y, s);
        s = fmaf(a.z, a.z, s); s = fmaf(a.w, a.w, s);
        float4 b = wd4[i];
        s = fmaf(b.x, b.x, s); s = fmaf(b.y, b.y, s);
        s = fmaf(b.z, b.z, s); s = fmaf(b.w, b.w, s);
    }
#pragma unroll
    for (int o = 16; o > 0; o >>= 1) s += __shfl_xor_sync(~0u, s, o);
    __shared__ float red[8];
    if ((threadIdx.x & 31) == 0) red[threadIdx.x >> 5] = s;
    __syncthreads();
    if (threadIdx.x == 0) {
        float tot = 0.f;
#pragma unroll
        for (int i = 0; i < 8; i++) tot += red[i];
        atomicAdd(&g_acc[2], tot);
    }
}

__global__ void finalize_kernel(float* __restrict__ out) {
    out[Bb * Pp + Nn] = (0.5f / (float)Bb) * g_acc[0] + 0.01f * g_acc[1] +
                        0.00025f * g_acc[2];
}

extern "C" void kernel_launch(void* const* d_in, const int* in_sizes, int n_in,
                              void* d_out, int out_size) {
    const float* x   = (const float*)d_in[0];
    const float* we  = (const float*)d_in[1];
    const float* be  = (const float*)d_in[2];
    const float* wd  = (const float*)d_in[3];
    const float* bd  = (const float*)d_in[4];
    const float* th  = (const float*)d_in[5];
    const float* cen = (const float*)d_in[6];
    float* out = (float*)d_out;

    gemm_enc<<<dim3(Nn / 64, Bb / 64), 256>>>(x, we, be);
    mle_kernel<<<Nn / 4, 128>>>(th, cen, out + Bb * Pp);
    decay_kernel<<<512, 256>>>(we, wd);
    gemm_dec<<<dim3(Pp / 64, Bb / 64), 256>>>(wd, bd, x, out);
    finalize_kernel<<<1, 1>>>(out);
}